// round 16
// baseline (speedup 1.0000x reference)
#include <cuda_runtime.h>
#include <cuda_fp16.h>

#define B_    16
#define C_    512
#define N_    1681
#define CK_   256
#define MPQ_  1792          // Q/K n-padding (14*128)
#define MP2_  1728          // attention m-padding (27*64)
#define XP_   1792          // x-split padding
#define NTT_  14
#define SCALE_ 0.0625f
#define EPS_  1e-5f

// ---------------- device scratch (all fp16 operands) ----------------
__device__ __half g_Qh[(size_t)B_*CK_*MPQ_];
__device__ __half g_Kh[(size_t)B_*CK_*MPQ_];
__device__ __half g_Xh[(size_t)B_*C_*XP_];
__device__ __half g_Sb[(size_t)B_*N_*MP2_];
__device__ __half g_Ah[(size_t)B_*N_*MP2_];
__device__ float g_pmin[B_*NTT_*N_], g_pss[B_*NTT_*N_], g_pfs[B_*NTT_*N_];

// ---------------- helpers ----------------
__device__ __forceinline__ unsigned s2u(const void* p) {
    unsigned a;
    asm("{ .reg .u64 t; cvta.to.shared.u64 t, %1; cvt.u32.u64 %0, t; }" : "=r"(a) : "l"(p));
    return a;
}
__device__ __forceinline__ void ldsm4(unsigned* r, unsigned a) {
    asm volatile("ldmatrix.sync.aligned.m8n8.x4.shared.b16 {%0,%1,%2,%3}, [%4];"
                 : "=r"(r[0]), "=r"(r[1]), "=r"(r[2]), "=r"(r[3]) : "r"(a));
}
__device__ __forceinline__ void ldsm4t(unsigned* r, unsigned a) {
    asm volatile("ldmatrix.sync.aligned.m8n8.x4.trans.shared.b16 {%0,%1,%2,%3}, [%4];"
                 : "=r"(r[0]), "=r"(r[1]), "=r"(r[2]), "=r"(r[3]) : "r"(a));
}
__device__ __forceinline__ void mma_h(float* c, const unsigned* a, unsigned b0, unsigned b1) {
    asm volatile("mma.sync.aligned.m16n8k16.row.col.f32.f16.f16.f32 "
                 "{%0,%1,%2,%3}, {%4,%5,%6,%7}, {%8,%9}, {%0,%1,%2,%3};"
                 : "+f"(c[0]), "+f"(c[1]), "+f"(c[2]), "+f"(c[3])
                 : "r"(a[0]), "r"(a[1]), "r"(a[2]), "r"(a[3]), "r"(b0), "r"(b1));
}
// kd32 helpers (proj): dir stride 80B, trn stride 272B
__device__ __forceinline__ void ldA_dir32(unsigned* a, unsigned tb, int mb, int ks, int L) {
    int q = L >> 3, rs = L & 7;
    ldsm4(a, tb + (unsigned)((mb + (q & 1) * 8 + rs) * 80 + (ks * 2 + (q >> 1)) * 16));
}
__device__ __forceinline__ void ldB_trn32(unsigned* b, unsigned tb, int nb, int ks, int L) {
    int q = L >> 3, rs = L & 7;
    ldsm4t(b, tb + (unsigned)((ks * 16 + (q & 1) * 8 + rs) * 272 + (nb + (q >> 1) * 8) * 2));
}
__device__ __forceinline__ unsigned pack_h2(float a0, float a1) {
    __half2 h;
    h.x = __float2half_rn(a0); h.y = __float2half_rn(a1);
    return *(unsigned*)&h;
}

// proj chunk: A dir(80B)/B trn(272B), kd=32, 1-product
__device__ __forceinline__ void gemm_proj(float (*acc)[4][4], unsigned ah,
                                          unsigned bh, int wm, int wn, int L)
{
    #pragma unroll
    for (int ks = 0; ks < 2; ks++) {
        unsigned aH[16], bH[8];
        #pragma unroll
        for (int fm = 0; fm < 4; fm++)
            ldA_dir32(aH + fm*4, ah, wm * 64 + fm * 16, ks, L);
        #pragma unroll
        for (int fp = 0; fp < 2; fp++)
            ldB_trn32(bH + fp*4, bh, wn * 32 + fp * 16, ks, L);
        #pragma unroll
        for (int fm = 0; fm < 4; fm++)
            #pragma unroll
            for (int fn = 0; fn < 4; fn++) {
                int bi = (fn >> 1) * 4 + (fn & 1) * 2;
                mma_h(acc[fm][fn], aH + fm*4, bH[bi], bH[bi+1]);
            }
    }
}

// sim chunk: both trn (stride 272B), kd=64, 1-product
__device__ __forceinline__ void gemm_sim64(float (*acc)[4][4], unsigned ah,
                                           unsigned bh, int wm, int wn, int L)
{
    int q = L >> 3, rs = L & 7;
    #pragma unroll
    for (int ks = 0; ks < 4; ks++) {
        unsigned aH[16], bH[8];
        #pragma unroll
        for (int fm = 0; fm < 4; fm++)
            ldsm4t(aH + fm*4, ah + (unsigned)((ks * 16 + (q >> 1) * 8 + rs) * 272
                                              + (wm * 64 + fm * 16 + (q & 1) * 8) * 2));
        #pragma unroll
        for (int fp = 0; fp < 2; fp++)
            ldsm4t(bH + fp*4, bh + (unsigned)((ks * 16 + (q & 1) * 8 + rs) * 272
                                              + (wn * 32 + fp * 16 + (q >> 1) * 8) * 2));
        #pragma unroll
        for (int fm = 0; fm < 4; fm++)
            #pragma unroll
            for (int fn = 0; fn < 4; fn++) {
                int bi = (fn >> 1) * 4 + (fn & 1) * 2;
                mma_h(acc[fm][fn], aH + fm*4, bH[bi], bH[bi+1]);
            }
    }
}

// ctx chunk: both dir (stride 144B), kd=64, 1-product
__device__ __forceinline__ void gemm_ctx64(float (*acc)[4][4], unsigned ah,
                                           unsigned bh, int wm, int wn, int L)
{
    int q = L >> 3, rs = L & 7;
    #pragma unroll
    for (int ks = 0; ks < 4; ks++) {
        unsigned aH[16], bH[8];
        #pragma unroll
        for (int fm = 0; fm < 4; fm++)
            ldsm4(aH + fm*4, ah + (unsigned)((wm * 64 + fm * 16 + (q & 1) * 8 + rs) * 144
                                             + (ks * 2 + (q >> 1)) * 16));
        #pragma unroll
        for (int fp = 0; fp < 2; fp++)
            ldsm4(bH + fp*4, bh + (unsigned)((wn * 32 + fp * 16 + (q >> 1) * 8 + rs) * 144
                                             + (ks * 2 + (q & 1)) * 16));
        #pragma unroll
        for (int fm = 0; fm < 4; fm++)
            #pragma unroll
            for (int fn = 0; fn < 4; fn++) {
                int bi = (fn >> 1) * 4 + (fn & 1) * 2;
                mma_h(acc[fm][fn], aH + fm*4, bH[bi], bH[bi+1]);
            }
    }
}

// ============ vprep: x -> padded fp16 [b][c][XP_], vectorized ============
__global__ __launch_bounds__(256)
void vprep(const float* __restrict__ x)
{
    int row = blockIdx.x;                 // b*C + c
    size_t xb = (size_t)row * N_, ob = (size_t)row * XP_;
    for (int g = threadIdx.x; g < XP_ / 4; g += 256) {
        int m = g * 4;
        float v[4];
        #pragma unroll
        for (int e = 0; e < 4; e++)
            v[e] = (m + e < N_) ? __ldg(x + xb + m + e) : 0.f;
        *(uint2*)(g_Xh + ob + m) = make_uint2(pack_h2(v[0], v[1]), pack_h2(v[2], v[3]));
    }
}

// ============ proj: D[k,n] = W@x + b (1-product fp16), store [b][k][n-pad] ============
__global__ __launch_bounds__(256, 2)
void proj_t(const float* __restrict__ Wq, const float* __restrict__ bq,
            const float* __restrict__ Wk, const float* __restrict__ bk)
{
    __shared__ __align__(16) char sm[10240 + 8704];
    unsigned sA = s2u(sm), sB = sA + 10240;
    int t = threadIdx.x, L = t & 31, w = t >> 5, wm = w & 1, wn = w >> 1;
    int z = blockIdx.z, b = z >> 1, isK = z & 1;
    const float* W    = isK ? Wk : Wq;
    const float* bias = isK ? bk : bq;
    __half* Oh = isK ? g_Kh : g_Qh;
    int n0 = blockIdx.x * 128, k0 = blockIdx.y * 128;
    const __half* Xh = g_Xh + (size_t)b * C_ * XP_;

    float acc[4][4][4] = {};
    for (int c0 = 0; c0 < C_; c0 += 32) {
        {   // A = W rows k -> fp16
            int r = t >> 1, hf = t & 1;
            const float4* Wp = (const float4*)(W + (size_t)(k0 + r) * C_ + c0 + hf * 16);
            unsigned hi[8];
            #pragma unroll
            for (int v = 0; v < 4; v++) {
                float4 f = Wp[v];
                hi[2*v]   = pack_h2(f.x, f.y);
                hi[2*v+1] = pack_h2(f.z, f.w);
            }
            unsigned off = r * 80 + hf * 32;
            *(uint4*)(sm + off)      = ((uint4*)hi)[0];
            *(uint4*)(sm + off + 16) = ((uint4*)hi)[1];
        }
        {   // B = x rows c, trans layout — uint4 copies from pre-split
            int r = t >> 3, seg = t & 7;
            size_t src = (size_t)(c0 + r) * XP_ + n0 + seg * 16;
            unsigned off = 10240 + r * 272 + seg * 32;
            *(uint4*)(sm + off)      = *(const uint4*)(Xh + src);
            *(uint4*)(sm + off + 16) = *(const uint4*)(Xh + src + 8);
        }
        __syncthreads();
        gemm_proj(acc, sA, sB, wm, wn, L);
        __syncthreads();
    }
    #pragma unroll
    for (int fm = 0; fm < 4; fm++) {
        #pragma unroll
        for (int rh = 0; rh < 2; rh++) {
            int k = k0 + wm * 64 + fm * 16 + (L >> 2) + rh * 8;
            float bia = bias[k];
            #pragma unroll
            for (int fn = 0; fn < 4; fn++) {
                int n = n0 + wn * 32 + fn * 8 + 2 * (L & 3);
                unsigned hp = pack_h2(acc[fm][fn][rh*2] + bia, acc[fm][fn][rh*2+1] + bia);
                *(unsigned*)(Oh + ((size_t)b * CK_ + k) * MPQ_ + n) = hp;
            }
        }
    }
}

// ============ sim: Sb[n,m] = fp16((Q.K^T)*scale*fg) + row stats (kd=64) ============
__global__ __launch_bounds__(256, 2)
void sim_t(const float* __restrict__ fg)
{
    __shared__ __align__(16) char sm[34816 + 6144];
    unsigned sQ = s2u(sm), sK = sQ + 17408;
    float* red = (float*)(sm + 34816);     // [3][8][64]
    int t = threadIdx.x, L = t & 31, w = t >> 5, wm = w & 1, wn = w >> 1;
    int b = blockIdx.z, m0 = blockIdx.x * 128, n0 = blockIdx.y * 128;

    float acc[4][4][4] = {};
    for (int k0 = 0; k0 < CK_; k0 += 64) {
        // fill: tile 0=Q rows n, 1=K rows m; [64 kd][128 cols] stride 272
        int tile = t >> 7;
        int idx = t & 127;
        int r = idx >> 1, hf = idx & 1;           // 64 rows x 2 threads, 128B each
        const __half* arr = tile ? g_Kh : g_Qh;
        int colb = tile ? m0 : n0;
        size_t src = ((size_t)b * CK_ + k0 + r) * MPQ_ + colb + hf * 64;
        unsigned d = (tile ? 17408u : 0u) + r * 272 + hf * 128;
        #pragma unroll
        for (int j = 0; j < 8; j++)
            *(uint4*)(sm + d + j * 16) = *(const uint4*)(arr + src + j * 8);
        __syncthreads();
        gemm_sim64(acc, sQ, sK, wm, wn, L);
        __syncthreads();
    }

    float rmn[4][2], rss[4][2], rfs[4][2];
    #pragma unroll
    for (int fm = 0; fm < 4; fm++)
        #pragma unroll
        for (int rh = 0; rh < 2; rh++) { rmn[fm][rh] = 3.4e38f; rss[fm][rh] = 0.f; rfs[fm][rh] = 0.f; }

    #pragma unroll
    for (int fm = 0; fm < 4; fm++)
        #pragma unroll
        for (int rh = 0; rh < 2; rh++) {
            int n = n0 + wm * 64 + fm * 16 + (L >> 2) + rh * 8;
            if (n < N_) {
                size_t fb = (size_t)b * N_ * N_ + (size_t)n * N_;
                size_t sbv = (size_t)b * N_ * MP2_ + (size_t)n * MP2_;
                #pragma unroll
                for (int fn = 0; fn < 4; fn++) {
                    int m = m0 + wn * 32 + fn * 8 + 2 * (L & 3);
                    float s0 = 0.f, s1v = 0.f;
                    if (m < N_) {
                        float f = __ldg(fg + fb + m);
                        s0 = acc[fm][fn][rh*2] * SCALE_ * f;
                        rmn[fm][rh] = fminf(rmn[fm][rh], s0);
                        rss[fm][rh] += s0 * f;
                        rfs[fm][rh] += f;
                    }
                    if (m + 1 < N_) {
                        float f = __ldg(fg + fb + m + 1);
                        s1v = acc[fm][fn][rh*2+1] * SCALE_ * f;
                        rmn[fm][rh] = fminf(rmn[fm][rh], s1v);
                        rss[fm][rh] += s1v * f;
                        rfs[fm][rh] += f;
                    }
                    if (m < N_)
                        *(unsigned*)(g_Sb + sbv + m) = pack_h2(s0, s1v);
                }
            }
        }
    #pragma unroll
    for (int fm = 0; fm < 4; fm++)
        #pragma unroll
        for (int rh = 0; rh < 2; rh++) {
            #pragma unroll
            for (int xr = 1; xr < 4; xr <<= 1) {
                rmn[fm][rh] = fminf(rmn[fm][rh], __shfl_xor_sync(0xFFFFFFFFu, rmn[fm][rh], xr));
                rss[fm][rh] += __shfl_xor_sync(0xFFFFFFFFu, rss[fm][rh], xr);
                rfs[fm][rh] += __shfl_xor_sync(0xFFFFFFFFu, rfs[fm][rh], xr);
            }
            if ((L & 3) == 0) {
                int ri = w * 64 + fm * 16 + rh * 8 + (L >> 2);
                red[ri] = rmn[fm][rh];
                red[512 + ri] = rss[fm][rh];
                red[1024 + ri] = rfs[fm][rh];
            }
        }
    __syncthreads();
    if (t < 128) {
        int hf = t >> 6, row = t & 63;
        float mn = 3.4e38f, ss = 0.f, fs = 0.f;
        #pragma unroll
        for (int j = 0; j < 4; j++) {
            int ww = hf + 2 * j;
            mn = fminf(mn, red[ww * 64 + row]);
            ss += red[512 + ww * 64 + row];
            fs += red[1024 + ww * 64 + row];
        }
        int n = n0 + hf * 64 + row;
        if (n < N_) {
            size_t idx = ((size_t)b * NTT_ + blockIdx.x) * N_ + n;
            g_pmin[idx] = mn; g_pss[idx] = ss; g_pfs[idx] = fs;
        }
    }
}

// ============ xform: finalize stats + A = fp16((Sb-min)*fg*inv + bg) ============
__global__ __launch_bounds__(256)
void xform(const float* __restrict__ fg, const float* __restrict__ bg)
{
    __shared__ float s_mn, s_iv;
    int r = blockIdx.x;               // b*N_ + n
    int t = threadIdx.x;
    int b = r / N_, n = r - b * N_;
    if (t < 32) {
        float mn = 3.4e38f, ss = 0.f, fs = 0.f;
        if (t < NTT_) {
            size_t idx = ((size_t)b * NTT_ + t) * N_ + n;
            mn = g_pmin[idx]; ss = g_pss[idx]; fs = g_pfs[idx];
        }
        #pragma unroll
        for (int xr = 16; xr > 0; xr >>= 1) {
            mn = fminf(mn, __shfl_xor_sync(0xFFFFFFFFu, mn, xr));
            ss += __shfl_xor_sync(0xFFFFFFFFu, ss, xr);
            fs += __shfl_xor_sync(0xFFFFFFFFu, fs, xr);
        }
        if (t == 0) { s_mn = mn; s_iv = 1.f / ((ss - mn * fs) + EPS_); }
    }
    __syncthreads();
    float mn = s_mn, iv = s_iv;
    size_t sbase = (size_t)r * MP2_;
    size_t gbase = (size_t)r * N_;
    for (int g = t; g < MP2_ / 4; g += 256) {
        int m = g * 4;
        float a[4];
        if (g < 420) {
            uint2 sp = *(const uint2*)(g_Sb + sbase + m);
            __half2 s01 = *(__half2*)&sp.x;
            __half2 s23 = *(__half2*)&sp.y;
            float sv[4] = { __half2float(s01.x), __half2float(s01.y),
                            __half2float(s23.x), __half2float(s23.y) };
            #pragma unroll
            for (int e = 0; e < 4; e++)
                a[e] = (sv[e] - mn) * __ldg(fg + gbase + m + e) * iv + __ldg(bg + gbase + m + e);
        } else if (g == 420) {
            #pragma unroll
            for (int e = 0; e < 4; e++) {
                int mm = m + e;
                if (mm < N_) {
                    float s1 = __half2float(g_Sb[sbase + mm]);
                    a[e] = (s1 - mn) * __ldg(fg + gbase + mm) * iv + __ldg(bg + gbase + mm);
                } else a[e] = 0.f;
            }
        } else {
            a[0] = a[1] = a[2] = a[3] = 0.f;
        }
        *(uint2*)(g_Ah + sbase + m) = make_uint2(pack_h2(a[0], a[1]), pack_h2(a[2], a[3]));
    }
}

// ============ ctx: out[c,n] = gamma*(attn @ x^T)[n,c] + x[c,n] (kd=64) ============
__global__ __launch_bounds__(256, 2)
void ctx_t(const float* __restrict__ x, const float* __restrict__ gamma,
           float* __restrict__ out)
{
    __shared__ __align__(16) char sm[36864];   // A 18432 + B 18432; epilogue reuses 33792
    unsigned sA = s2u(sm), sB = sA + 18432;
    int t = threadIdx.x, L = t & 31, w = t >> 5, wm = w & 1, wn = w >> 1;
    int b = blockIdx.z, n0 = blockIdx.x * 128, c0 = blockIdx.y * 128;
    const __half* Xh = g_Xh + (size_t)b * C_ * XP_;

    float acc[4][4][4] = {};
    for (int m0 = 0; m0 < MP2_; m0 += 64) {
        int r = t >> 1, hf = t & 1;     // 128 rows x 2 threads; 64B (4 uint4) each
        {   // A = attn rows n (zero-pad n>=N rows)
            int n = n0 + r;
            unsigned off = r * 144 + hf * 64;
            if (n < N_) {
                size_t ai = ((size_t)b * N_ + n) * MP2_ + m0 + hf * 32;
                #pragma unroll
                for (int j = 0; j < 4; j++)
                    *(uint4*)(sm + off + j * 16) = *(const uint4*)(g_Ah + ai + j * 8);
            } else {
                uint4 z = make_uint4(0, 0, 0, 0);
                #pragma unroll
                for (int j = 0; j < 4; j++)
                    *(uint4*)(sm + off + j * 16) = z;
            }
        }
        {   // B = x rows c
            size_t src = (size_t)(c0 + r) * XP_ + m0 + hf * 32;
            unsigned off = 18432 + r * 144 + hf * 64;
            #pragma unroll
            for (int j = 0; j < 4; j++)
                *(uint4*)(sm + off + j * 16) = *(const uint4*)(Xh + src + j * 8);
        }
        __syncthreads();
        gemm_ctx64(acc, sA, sB, wm, wn, L);
        __syncthreads();
    }

    float gam = __ldg(gamma);
    float* stage = (float*)sm;
    #pragma unroll 1
    for (int ch = 0; ch < 2; ch++) {
        if ((wn >> 1) == ch) {
            #pragma unroll
            for (int fm = 0; fm < 4; fm++)
                #pragma unroll
                for (int fn = 0; fn < 4; fn++)
                    #pragma unroll
                    for (int e = 0; e < 4; e++) {
                        int cl = (wn & 1) * 32 + fn * 8 + 2 * (L & 3) + (e & 1);
                        int nl = wm * 64 + fm * 16 + (L >> 2) + (e >> 1) * 8;
                        stage[cl * 132 + nl] = acc[fm][fn][e];
                    }
        }
        __syncthreads();
        #pragma unroll 1
        for (int rr = 0; rr < 8; rr++) {
            int cc = w * 8 + rr;
            int c = c0 + ch * 64 + cc;
            size_t ob = ((size_t)b * C_ + c) * N_;
            #pragma unroll
            for (int jj = 0; jj < 4; jj++) {
                int n = n0 + jj * 32 + L;
                if (n < N_)
                    out[ob + n] = gam * stage[cc * 132 + jj * 32 + L] + __ldg(x + ob + n);
            }
        }
        __syncthreads();
    }
}

// ============================================================
extern "C" void kernel_launch(void* const* d_in, const int* in_sizes, int n_in,
                              void* d_out, int out_size)
{
    const float* x     = (const float*)d_in[0];
    const float* fg    = (const float*)d_in[1];
    const float* bg    = (const float*)d_in[2];
    const float* Wq    = (const float*)d_in[3];
    const float* bq    = (const float*)d_in[4];
    const float* Wk    = (const float*)d_in[5];
    const float* bk    = (const float*)d_in[6];
    const float* gamma = (const float*)d_in[7];
    float* out = (float*)d_out;

    vprep<<<B_ * C_, 256>>>(x);
    proj_t<<<dim3(14, 2, 32), 256>>>(Wq, bq, Wk, bk);
    sim_t<<<dim3(14, 14, 16), 256>>>(fg);
    xform<<<B_ * N_, 256>>>(fg, bg);
    ctx_t<<<dim3(14, 4, 16), 256>>>(x, gamma, out);
}

// round 17
// speedup vs baseline: 1.0388x; 1.0388x over previous
#include <cuda_runtime.h>
#include <cuda_fp16.h>

#define B_    16
#define C_    512
#define N_    1681
#define CK_   256
#define MPQ_  1792          // Q/K n-padding (14*128)
#define MP2_  1728          // attention m-padding (54*32)
#define XP_   1792          // x-split padding
#define NTT_  14
#define SCALE_ 0.0625f
#define EPS_  1e-5f

// ---------------- device scratch (all fp16 operands) ----------------
__device__ __half g_Qh[(size_t)B_*CK_*MPQ_];
__device__ __half g_Kh[(size_t)B_*CK_*MPQ_];
__device__ __half g_Xh[(size_t)B_*C_*XP_];
__device__ __half g_Sb[(size_t)B_*N_*MP2_];
__device__ __half g_Ah[(size_t)B_*N_*MP2_];
__device__ float g_pmin[B_*NTT_*N_], g_pss[B_*NTT_*N_], g_pfs[B_*NTT_*N_];

// ---------------- helpers ----------------
__device__ __forceinline__ unsigned s2u(const void* p) {
    unsigned a;
    asm("{ .reg .u64 t; cvta.to.shared.u64 t, %1; cvt.u32.u64 %0, t; }" : "=r"(a) : "l"(p));
    return a;
}
__device__ __forceinline__ void ldsm4(unsigned* r, unsigned a) {
    asm volatile("ldmatrix.sync.aligned.m8n8.x4.shared.b16 {%0,%1,%2,%3}, [%4];"
                 : "=r"(r[0]), "=r"(r[1]), "=r"(r[2]), "=r"(r[3]) : "r"(a));
}
__device__ __forceinline__ void ldsm4t(unsigned* r, unsigned a) {
    asm volatile("ldmatrix.sync.aligned.m8n8.x4.trans.shared.b16 {%0,%1,%2,%3}, [%4];"
                 : "=r"(r[0]), "=r"(r[1]), "=r"(r[2]), "=r"(r[3]) : "r"(a));
}
__device__ __forceinline__ void mma_h(float* c, const unsigned* a, unsigned b0, unsigned b1) {
    asm volatile("mma.sync.aligned.m16n8k16.row.col.f32.f16.f16.f32 "
                 "{%0,%1,%2,%3}, {%4,%5,%6,%7}, {%8,%9}, {%0,%1,%2,%3};"
                 : "+f"(c[0]), "+f"(c[1]), "+f"(c[2]), "+f"(c[3])
                 : "r"(a[0]), "r"(a[1]), "r"(a[2]), "r"(a[3]), "r"(b0), "r"(b1));
}
// direct tile: [row128][kd32] fp16, stride 80B. trans tile: [kd32][col128] fp16, stride 272B.
__device__ __forceinline__ void ldA_dir(unsigned* a, unsigned tb, int mb, int ks, int L) {
    int q = L >> 3, rs = L & 7;
    ldsm4(a, tb + (unsigned)((mb + (q & 1) * 8 + rs) * 80 + (ks * 2 + (q >> 1)) * 16));
}
__device__ __forceinline__ void ldA_trn(unsigned* a, unsigned tb, int mb, int ks, int L) {
    int q = L >> 3, rs = L & 7;
    ldsm4t(a, tb + (unsigned)((ks * 16 + (q >> 1) * 8 + rs) * 272 + (mb + (q & 1) * 8) * 2));
}
__device__ __forceinline__ void ldB_dir(unsigned* b, unsigned tb, int nb, int ks, int L) {
    int q = L >> 3, rs = L & 7;
    ldsm4(b, tb + (unsigned)((nb + (q >> 1) * 8 + rs) * 80 + (ks * 2 + (q & 1)) * 16));
}
__device__ __forceinline__ void ldB_trn(unsigned* b, unsigned tb, int nb, int ks, int L) {
    int q = L >> 3, rs = L & 7;
    ldsm4t(b, tb + (unsigned)((ks * 16 + (q & 1) * 8 + rs) * 272 + (nb + (q >> 1) * 8) * 2));
}
__device__ __forceinline__ unsigned pack_h2(float a0, float a1) {
    __half2 h;
    h.x = __float2half_rn(a0); h.y = __float2half_rn(a1);
    return *(unsigned*)&h;
}

// 1-product chunk, kd=32
template<int AT, int BT>
__device__ __forceinline__ void gemm_chunk1(float (*acc)[4][4], unsigned ah,
                                            unsigned bh, int wm, int wn, int L)
{
    #pragma unroll
    for (int ks = 0; ks < 2; ks++) {
        unsigned aH[16], bH[8];
        #pragma unroll
        for (int fm = 0; fm < 4; fm++) {
            if (AT) ldA_trn(aH + fm*4, ah, wm * 64 + fm * 16, ks, L);
            else    ldA_dir(aH + fm*4, ah, wm * 64 + fm * 16, ks, L);
        }
        #pragma unroll
        for (int fp = 0; fp < 2; fp++) {
            if (BT) ldB_trn(bH + fp*4, bh, wn * 32 + fp * 16, ks, L);
            else    ldB_dir(bH + fp*4, bh, wn * 32 + fp * 16, ks, L);
        }
        #pragma unroll
        for (int fm = 0; fm < 4; fm++)
            #pragma unroll
            for (int fn = 0; fn < 4; fn++) {
                int bi = (fn >> 1) * 4 + (fn & 1) * 2;
                mma_h(acc[fm][fn], aH + fm*4, bH[bi], bH[bi+1]);
            }
    }
}

// ============ vprep: x -> padded fp16 [b][c][XP_], vectorized ============
__global__ __launch_bounds__(256)
void vprep(const float* __restrict__ x)
{
    int row = blockIdx.x;                 // b*C + c
    size_t xb = (size_t)row * N_, ob = (size_t)row * XP_;
    for (int g = threadIdx.x; g < XP_ / 4; g += 256) {
        int m = g * 4;
        float v[4];
        #pragma unroll
        for (int e = 0; e < 4; e++)
            v[e] = (m + e < N_) ? __ldg(x + xb + m + e) : 0.f;
        *(uint2*)(g_Xh + ob + m) = make_uint2(pack_h2(v[0], v[1]), pack_h2(v[2], v[3]));
    }
}

// ============ proj: D[k,n] = W@x + b (1-product fp16), store [b][k][n-pad] ============
__global__ __launch_bounds__(256, 2)
void proj_t(const float* __restrict__ Wq, const float* __restrict__ bq,
            const float* __restrict__ Wk, const float* __restrict__ bk)
{
    __shared__ __align__(16) char sm[10240 + 8704];
    unsigned sA = s2u(sm), sB = sA + 10240;
    int t = threadIdx.x, L = t & 31, w = t >> 5, wm = w & 1, wn = w >> 1;
    int z = blockIdx.z, b = z >> 1, isK = z & 1;
    const float* W    = isK ? Wk : Wq;
    const float* bias = isK ? bk : bq;
    __half* Oh = isK ? g_Kh : g_Qh;
    int n0 = blockIdx.x * 128, k0 = blockIdx.y * 128;
    const __half* Xh = g_Xh + (size_t)b * C_ * XP_;

    float acc[4][4][4] = {};
    for (int c0 = 0; c0 < C_; c0 += 32) {
        {   // A = W rows k -> fp16
            int r = t >> 1, hf = t & 1;
            const float4* Wp = (const float4*)(W + (size_t)(k0 + r) * C_ + c0 + hf * 16);
            unsigned hi[8];
            #pragma unroll
            for (int v = 0; v < 4; v++) {
                float4 f = Wp[v];
                hi[2*v]   = pack_h2(f.x, f.y);
                hi[2*v+1] = pack_h2(f.z, f.w);
            }
            unsigned off = r * 80 + hf * 32;
            *(uint4*)(sm + off)      = ((uint4*)hi)[0];
            *(uint4*)(sm + off + 16) = ((uint4*)hi)[1];
        }
        {   // B = x rows c, trans layout — uint4 copies from pre-split
            int r = t >> 3, seg = t & 7;
            size_t src = (size_t)(c0 + r) * XP_ + n0 + seg * 16;
            unsigned off = 10240 + r * 272 + seg * 32;
            *(uint4*)(sm + off)      = *(const uint4*)(Xh + src);
            *(uint4*)(sm + off + 16) = *(const uint4*)(Xh + src + 8);
        }
        __syncthreads();
        gemm_chunk1<0, 1>(acc, sA, sB, wm, wn, L);
        __syncthreads();
    }
    #pragma unroll
    for (int fm = 0; fm < 4; fm++) {
        #pragma unroll
        for (int rh = 0; rh < 2; rh++) {
            int k = k0 + wm * 64 + fm * 16 + (L >> 2) + rh * 8;
            float bia = bias[k];
            #pragma unroll
            for (int fn = 0; fn < 4; fn++) {
                int n = n0 + wn * 32 + fn * 8 + 2 * (L & 3);
                unsigned hp = pack_h2(acc[fm][fn][rh*2] + bia, acc[fm][fn][rh*2+1] + bia);
                *(unsigned*)(Oh + ((size_t)b * CK_ + k) * MPQ_ + n) = hp;
            }
        }
    }
}

// ============ sim: Sb[n,m] = fp16((Q.K^T)*scale*fg) + row stats (1-product fp16) ============
__global__ __launch_bounds__(256, 2)
void sim_t(const float* __restrict__ fg)
{
    __shared__ __align__(16) char sm[17408 + 6144];
    unsigned sQ = s2u(sm), sK = sQ + 8704;
    float* red = (float*)(sm + 17408);     // [3][8][64]
    int t = threadIdx.x, L = t & 31, w = t >> 5, wm = w & 1, wn = w >> 1;
    int b = blockIdx.z, m0 = blockIdx.x * 128, n0 = blockIdx.y * 128;

    float acc[4][4][4] = {};
    for (int k0 = 0; k0 < CK_; k0 += 32) {
        int r = t >> 3, seg = t & 7;
        size_t qi = ((size_t)b * CK_ + k0 + r) * MPQ_ + n0 + seg * 16;
        size_t ki = ((size_t)b * CK_ + k0 + r) * MPQ_ + m0 + seg * 16;
        unsigned off = r * 272 + seg * 32;
        *(uint4*)(sm + off)             = *(const uint4*)(g_Qh + qi);
        *(uint4*)(sm + off + 16)        = *(const uint4*)(g_Qh + qi + 8);
        *(uint4*)(sm + 8704 + off)      = *(const uint4*)(g_Kh + ki);
        *(uint4*)(sm + 8704 + off + 16) = *(const uint4*)(g_Kh + ki + 8);
        __syncthreads();
        gemm_chunk1<1, 1>(acc, sQ, sK, wm, wn, L);
        __syncthreads();
    }

    float rmn[4][2], rss[4][2], rfs[4][2];
    #pragma unroll
    for (int fm = 0; fm < 4; fm++)
        #pragma unroll
        for (int rh = 0; rh < 2; rh++) { rmn[fm][rh] = 3.4e38f; rss[fm][rh] = 0.f; rfs[fm][rh] = 0.f; }

    #pragma unroll
    for (int fm = 0; fm < 4; fm++)
        #pragma unroll
        for (int rh = 0; rh < 2; rh++) {
            int n = n0 + wm * 64 + fm * 16 + (L >> 2) + rh * 8;
            if (n < N_) {
                size_t fb = (size_t)b * N_ * N_ + (size_t)n * N_;
                size_t sbv = (size_t)b * N_ * MP2_ + (size_t)n * MP2_;
                #pragma unroll
                for (int fn = 0; fn < 4; fn++) {
                    int m = m0 + wn * 32 + fn * 8 + 2 * (L & 3);
                    float s0 = 0.f, s1v = 0.f;
                    if (m < N_) {
                        float f = __ldg(fg + fb + m);
                        s0 = acc[fm][fn][rh*2] * SCALE_ * f;
                        rmn[fm][rh] = fminf(rmn[fm][rh], s0);
                        rss[fm][rh] += s0 * f;
                        rfs[fm][rh] += f;
                    }
                    if (m + 1 < N_) {
                        float f = __ldg(fg + fb + m + 1);
                        s1v = acc[fm][fn][rh*2+1] * SCALE_ * f;
                        rmn[fm][rh] = fminf(rmn[fm][rh], s1v);
                        rss[fm][rh] += s1v * f;
                        rfs[fm][rh] += f;
                    }
                    if (m < N_)
                        *(unsigned*)(g_Sb + sbv + m) = pack_h2(s0, s1v);
                }
            }
        }
    #pragma unroll
    for (int fm = 0; fm < 4; fm++)
        #pragma unroll
        for (int rh = 0; rh < 2; rh++) {
            #pragma unroll
            for (int xr = 1; xr < 4; xr <<= 1) {
                rmn[fm][rh] = fminf(rmn[fm][rh], __shfl_xor_sync(0xFFFFFFFFu, rmn[fm][rh], xr));
                rss[fm][rh] += __shfl_xor_sync(0xFFFFFFFFu, rss[fm][rh], xr);
                rfs[fm][rh] += __shfl_xor_sync(0xFFFFFFFFu, rfs[fm][rh], xr);
            }
            if ((L & 3) == 0) {
                int ri = w * 64 + fm * 16 + rh * 8 + (L >> 2);
                red[ri] = rmn[fm][rh];
                red[512 + ri] = rss[fm][rh];
                red[1024 + ri] = rfs[fm][rh];
            }
        }
    __syncthreads();
    if (t < 128) {
        int hf = t >> 6, row = t & 63;
        float mn = 3.4e38f, ss = 0.f, fs = 0.f;
        #pragma unroll
        for (int j = 0; j < 4; j++) {
            int ww = hf + 2 * j;
            mn = fminf(mn, red[ww * 64 + row]);
            ss += red[512 + ww * 64 + row];
            fs += red[1024 + ww * 64 + row];
        }
        int n = n0 + hf * 64 + row;
        if (n < N_) {
            size_t idx = ((size_t)b * NTT_ + blockIdx.x) * N_ + n;
            g_pmin[idx] = mn; g_pss[idx] = ss; g_pfs[idx] = fs;
        }
    }
}

// ============ xform: finalize stats + A = fp16((Sb-min)*fg*inv + bg) ============
__global__ __launch_bounds__(256)
void xform(const float* __restrict__ fg, const float* __restrict__ bg)
{
    __shared__ float s_mn, s_iv;
    int r = blockIdx.x;               // b*N_ + n
    int t = threadIdx.x;
    int b = r / N_, n = r - b * N_;
    if (t < 32) {
        float mn = 3.4e38f, ss = 0.f, fs = 0.f;
        if (t < NTT_) {
            size_t idx = ((size_t)b * NTT_ + t) * N_ + n;
            mn = g_pmin[idx]; ss = g_pss[idx]; fs = g_pfs[idx];
        }
        #pragma unroll
        for (int xr = 16; xr > 0; xr >>= 1) {
            mn = fminf(mn, __shfl_xor_sync(0xFFFFFFFFu, mn, xr));
            ss += __shfl_xor_sync(0xFFFFFFFFu, ss, xr);
            fs += __shfl_xor_sync(0xFFFFFFFFu, fs, xr);
        }
        if (t == 0) { s_mn = mn; s_iv = 1.f / ((ss - mn * fs) + EPS_); }
    }
    __syncthreads();
    float mn = s_mn, iv = s_iv;
    size_t sbase = (size_t)r * MP2_;
    size_t gbase = (size_t)r * N_;
    for (int g = t; g < MP2_ / 4; g += 256) {
        int m = g * 4;
        float a[4];
        if (g < 420) {
            uint2 sp = *(const uint2*)(g_Sb + sbase + m);
            __half2 s01 = *(__half2*)&sp.x;
            __half2 s23 = *(__half2*)&sp.y;
            float sv[4] = { __half2float(s01.x), __half2float(s01.y),
                            __half2float(s23.x), __half2float(s23.y) };
            #pragma unroll
            for (int e = 0; e < 4; e++)
                a[e] = (sv[e] - mn) * __ldg(fg + gbase + m + e) * iv + __ldg(bg + gbase + m + e);
        } else if (g == 420) {
            #pragma unroll
            for (int e = 0; e < 4; e++) {
                int mm = m + e;
                if (mm < N_) {
                    float s1 = __half2float(g_Sb[sbase + mm]);
                    a[e] = (s1 - mn) * __ldg(fg + gbase + mm) * iv + __ldg(bg + gbase + mm);
                } else a[e] = 0.f;
            }
        } else {
            a[0] = a[1] = a[2] = a[3] = 0.f;
        }
        *(uint2*)(g_Ah + sbase + m) = make_uint2(pack_h2(a[0], a[1]), pack_h2(a[2], a[3]));
    }
}

// ============ ctx: out[c,n] = gamma*(attn @ x^T)[n,c] + x[c,n] (1-product fp16) ============
// grid = (4 c-tiles, 14 n-tiles, 16 b): A-sharing CTAs adjacent for L2 locality
__global__ __launch_bounds__(256, 2)
void ctx_t(const float* __restrict__ x, const float* __restrict__ gamma,
           float* __restrict__ out)
{
    __shared__ __align__(16) char sm[34816];   // epilogue staging needs 33792
    unsigned sA = s2u(sm), sB = sA + 10240;
    int t = threadIdx.x, L = t & 31, w = t >> 5, wm = w & 1, wn = w >> 1;
    int b = blockIdx.z, n0 = blockIdx.y * 128, c0 = blockIdx.x * 128;
    const __half* Xh = g_Xh + (size_t)b * C_ * XP_;

    float acc[4][4][4] = {};
    for (int m0 = 0; m0 < MP2_; m0 += 32) {
        int r = t >> 1, hf = t & 1;
        {   // A = attn rows n (uint4, zero-pad n>=N rows)
            int n = n0 + r;
            unsigned off = r * 80 + hf * 32;
            if (n < N_) {
                size_t ai = ((size_t)b * N_ + n) * MP2_ + m0 + hf * 16;
                *(uint4*)(sm + off)      = *(const uint4*)(g_Ah + ai);
                *(uint4*)(sm + off + 16) = *(const uint4*)(g_Ah + ai + 8);
            } else {
                uint4 z = make_uint4(0, 0, 0, 0);
                *(uint4*)(sm + off) = z; *(uint4*)(sm + off + 16) = z;
            }
        }
        {   // B = x rows c — uint4 copies
            size_t src = (size_t)(c0 + r) * XP_ + m0 + hf * 16;
            unsigned off = 10240 + r * 80 + hf * 32;
            *(uint4*)(sm + off)      = *(const uint4*)(Xh + src);
            *(uint4*)(sm + off + 16) = *(const uint4*)(Xh + src + 8);
        }
        __syncthreads();
        gemm_chunk1<0, 0>(acc, sA, sB, wm, wn, L);
        __syncthreads();
    }

    float gam = __ldg(gamma);
    float* stage = (float*)sm;
    #pragma unroll 1
    for (int ch = 0; ch < 2; ch++) {
        if ((wn >> 1) == ch) {
            #pragma unroll
            for (int fm = 0; fm < 4; fm++)
                #pragma unroll
                for (int fn = 0; fn < 4; fn++)
                    #pragma unroll
                    for (int e = 0; e < 4; e++) {
                        int cl = (wn & 1) * 32 + fn * 8 + 2 * (L & 3) + (e & 1);
                        int nl = wm * 64 + fm * 16 + (L >> 2) + (e >> 1) * 8;
                        stage[cl * 132 + nl] = acc[fm][fn][e];
                    }
        }
        __syncthreads();
        #pragma unroll 1
        for (int rr = 0; rr < 8; rr++) {
            int cc = w * 8 + rr;
            int c = c0 + ch * 64 + cc;
            size_t ob = ((size_t)b * C_ + c) * N_;
            #pragma unroll
            for (int jj = 0; jj < 4; jj++) {
                int n = n0 + jj * 32 + L;
                if (n < N_)
                    out[ob + n] = gam * stage[cc * 132 + jj * 32 + L] + __ldg(x + ob + n);
            }
        }
        __syncthreads();
    }
}

// ============================================================
extern "C" void kernel_launch(void* const* d_in, const int* in_sizes, int n_in,
                              void* d_out, int out_size)
{
    const float* x     = (const float*)d_in[0];
    const float* fg    = (const float*)d_in[1];
    const float* bg    = (const float*)d_in[2];
    const float* Wq    = (const float*)d_in[3];
    const float* bq    = (const float*)d_in[4];
    const float* Wk    = (const float*)d_in[5];
    const float* bk    = (const float*)d_in[6];
    const float* gamma = (const float*)d_in[7];
    float* out = (float*)d_out;

    vprep<<<B_ * C_, 256>>>(x);
    proj_t<<<dim3(14, 2, 32), 256>>>(Wq, bq, Wk, bk);
    sim_t<<<dim3(14, 14, 16), 256>>>(fg);
    xform<<<B_ * N_, 256>>>(fg, bg);
    ctx_t<<<dim3(4, 14, 16), 256>>>(x, gamma, out);
}